// round 12
// baseline (speedup 1.0000x reference)
#include <cuda_runtime.h>
#include <math.h>
#include <stdint.h>

#define B_   8
#define T_   512
#define FIN_ 256
#define D_   128
#define C_   16          // chunks per batch
#define L_   32          // chunk length (T_/C_)
#define SUB_ 16          // sub-tile of timesteps in k4 smem

// ---------------- scratch ----------------
__device__ __align__(16) float g_XN[B_*T_*FIN_];
__device__ __align__(16) float g_K[B_*T_*D_];
__device__ __align__(16) float g_Q[B_*T_*D_];
__device__ __align__(16) float g_V[B_*T_*D_];
__device__ __align__(16) float g_R[B_*T_*D_];
__device__ __align__(16) float g_Ssum[B_*C_*D_*D_];  // RAW per-chunk outer sums
__device__ __align__(16) float g_Zsum[B_*C_*D_];     // RAW per-chunk K sums

// ---------------- tf32 helpers ----------------
__device__ __forceinline__ uint32_t f2tf32(float x) {
    uint32_t r; asm("cvt.rna.tf32.f32 %0, %1;" : "=r"(r) : "f"(x)); return r;
}
__device__ __forceinline__ void mma_tf32(float* d, const uint32_t* a, const uint32_t* b) {
    asm volatile(
        "mma.sync.aligned.m16n8k8.row.col.f32.tf32.tf32.f32 "
        "{%0,%1,%2,%3}, {%4,%5,%6,%7}, {%8,%9}, {%0,%1,%2,%3};"
        : "+f"(d[0]), "+f"(d[1]), "+f"(d[2]), "+f"(d[3])
        : "r"(a[0]), "r"(a[1]), "r"(a[2]), "r"(a[3]), "r"(b[0]), "r"(b[1]));
}

// ---------------- k0: LayerNorm -> g_XN ----------------
__global__ void k0_ln(const float* __restrict__ x,
                      const float* __restrict__ gamma, const float* __restrict__ beta) {
    const int tid  = threadIdx.x;
    const int w    = tid >> 5, lane = tid & 31;
    const int row0 = blockIdx.x * 32;

    float gv[8], bv[8];
#pragma unroll
    for (int k = 0; k < 8; k++) { gv[k] = gamma[lane + 32*k]; bv[k] = beta[lane + 32*k]; }

#pragma unroll
    for (int rr = 0; rr < 4; rr++) {
        const size_t r = (size_t)row0 + w*4 + rr;
        float s = 0.f, ss = 0.f, xv[8];
#pragma unroll
        for (int k = 0; k < 8; k++) {
            float v = x[r*FIN_ + lane + 32*k];
            xv[k] = v; s += v; ss += v*v;
        }
#pragma unroll
        for (int off = 16; off; off >>= 1) {
            s  += __shfl_xor_sync(0xffffffffu, s,  off);
            ss += __shfl_xor_sync(0xffffffffu, ss, off);
        }
        const float mu   = s * (1.0f/FIN_);
        const float rstd = rsqrtf(ss*(1.0f/FIN_) - mu*mu + 1e-5f);
#pragma unroll
        for (int k = 0; k < 8; k++)
            g_XN[r*FIN_ + lane + 32*k] = (xv[k]-mu)*rstd*gv[k] + bv[k];
    }
}

// ---------------- k1: tf32 tensor-core projections, 3xTF32 split ----------------
#define XP 36
#define WP 132
#define K1_SMEM ((2*64*XP + 2*32*WP) * 4)   // 52224 B
__global__ void __launch_bounds__(256)
k1_tf32(const float* __restrict__ Wk, const float* __restrict__ Wq,
        const float* __restrict__ Wv, const float* __restrict__ Ws,
        const float* __restrict__ bs) {
    extern __shared__ uint32_t su[];
    uint32_t* xh = su;
    uint32_t* xl = xh + 64*XP;
    uint32_t* wh = xl + 64*XP;
    uint32_t* wl = wh + 32*WP;

    const int tid  = threadIdx.x;
    const int lane = tid & 31;
    const int wid  = tid >> 5;
    const int wm   = wid >> 1;
    const int wn   = wid & 1;
    const int g    = lane >> 2;
    const int t    = lane & 3;
    const int row0 = blockIdx.x * 64;
    const int m    = blockIdx.y;

    const float* Wp = (m==0) ? Wk : (m==1) ? Wq : (m==2) ? Wv : Ws;
    float*       Op = (m==0) ? g_K : (m==1) ? g_Q : (m==2) ? g_V : g_R;

    float d[8][4];
#pragma unroll
    for (int nt = 0; nt < 8; nt++)
#pragma unroll
        for (int q = 0; q < 4; q++) d[nt][q] = 0.f;

    for (int kc = 0; kc < FIN_; kc += 32) {
        __syncthreads();
#pragma unroll
        for (int p = 0; p < 2; p++) {
            const int idx = p*256 + tid;
            const int r = idx >> 3, c4 = (idx & 7) * 4;
            const float4 v = *(const float4*)(g_XN + ((size_t)row0 + r)*FIN_ + kc + c4);
            uint4 h, l;
            h.x = f2tf32(v.x); l.x = f2tf32(v.x - __uint_as_float(h.x));
            h.y = f2tf32(v.y); l.y = f2tf32(v.y - __uint_as_float(h.y));
            h.z = f2tf32(v.z); l.z = f2tf32(v.z - __uint_as_float(h.z));
            h.w = f2tf32(v.w); l.w = f2tf32(v.w - __uint_as_float(h.w));
            *(uint4*)&xh[r*XP + c4] = h;
            *(uint4*)&xl[r*XP + c4] = l;
        }
#pragma unroll
        for (int p = 0; p < 4; p++) {
            const int idx = p*256 + tid;
            const int r = idx >> 5, c4 = (idx & 31) * 4;
            const float4 v = *(const float4*)(Wp + ((size_t)kc + r)*D_ + c4);
            uint4 h, l;
            h.x = f2tf32(v.x); l.x = f2tf32(v.x - __uint_as_float(h.x));
            h.y = f2tf32(v.y); l.y = f2tf32(v.y - __uint_as_float(h.y));
            h.z = f2tf32(v.z); l.z = f2tf32(v.z - __uint_as_float(h.z));
            h.w = f2tf32(v.w); l.w = f2tf32(v.w - __uint_as_float(h.w));
            *(uint4*)&wh[r*WP + c4] = h;
            *(uint4*)&wl[r*WP + c4] = l;
        }
        __syncthreads();

#pragma unroll
        for (int ks = 0; ks < 4; ks++) {
            const int ko = ks * 8;
            const int m0 = wm * 16;
            uint32_t ah[4], al[4];
            ah[0] = xh[(m0+g)*XP   + ko + t];
            ah[1] = xh[(m0+g+8)*XP + ko + t];
            ah[2] = xh[(m0+g)*XP   + ko + t + 4];
            ah[3] = xh[(m0+g+8)*XP + ko + t + 4];
            al[0] = xl[(m0+g)*XP   + ko + t];
            al[1] = xl[(m0+g+8)*XP + ko + t];
            al[2] = xl[(m0+g)*XP   + ko + t + 4];
            al[3] = xl[(m0+g+8)*XP + ko + t + 4];
#pragma unroll
            for (int nt = 0; nt < 8; nt++) {
                const int n0 = wn*64 + nt*8;
                uint32_t bh[2], bl[2];
                bh[0] = wh[(ko+t)*WP   + n0 + g];
                bh[1] = wh[(ko+t+4)*WP + n0 + g];
                bl[0] = wl[(ko+t)*WP   + n0 + g];
                bl[1] = wl[(ko+t+4)*WP + n0 + g];
                mma_tf32(d[nt], ah, bh);
                mma_tf32(d[nt], ah, bl);
                mma_tf32(d[nt], al, bh);
            }
        }
    }

#pragma unroll
    for (int nt = 0; nt < 8; nt++) {
        const int n0 = wn*64 + nt*8;
        const int cA = n0 + t*2;
        float v0 = d[nt][0], v1 = d[nt][1], v2 = d[nt][2], v3 = d[nt][3];
        if (m <= 1) {
            v0 = (v0 > 0.f) ? (v0 + 1.f) : expf(v0);
            v1 = (v1 > 0.f) ? (v1 + 1.f) : expf(v1);
            v2 = (v2 > 0.f) ? (v2 + 1.f) : expf(v2);
            v3 = (v3 > 0.f) ? (v3 + 1.f) : expf(v3);
        } else if (m == 3) {
            const float b0 = bs[cA], b1 = bs[cA+1];
            v0 += b0; v1 += b1; v2 += b0; v3 += b1;
        }
        const size_t r0 = (size_t)row0 + wm*16 + g;
        *(float2*)(Op + r0*D_ + cA)       = make_float2(v0, v1);
        *(float2*)(Op + (r0+8)*D_ + cA)   = make_float2(v2, v3);
    }
}

// ---------------- k2: per-chunk outer-product sums + K sums (RAW) ----------------
__global__ void k2_chunksum() {
    const int c = blockIdx.x, b = blockIdx.y;
    const int tid = threadIdx.x;   // 256
    __shared__ __align__(16) float Ks[L_][D_];
    __shared__ __align__(16) float Vs[L_][D_];
    {
        const float4* kg = (const float4*)(g_K + ((size_t)b*T_ + c*L_)*D_);
        const float4* vg = (const float4*)(g_V + ((size_t)b*T_ + c*L_)*D_);
        for (int q = tid; q < L_*D_/4; q += 256) { ((float4*)Ks)[q] = kg[q]; ((float4*)Vs)[q] = vg[q]; }
    }
    __syncthreads();

    if (tid < D_) {
        float zs = 0.f;
#pragma unroll
        for (int t = 0; t < L_; t++) zs += Ks[t][tid];
        g_Zsum[((size_t)(b*C_ + c))*D_ + tid] = zs;
    }

    const int tr = tid >> 4, tc = tid & 15;
    const int i0 = tr*8, j0 = tc*8;
    float acc[8][8];
#pragma unroll
    for (int u = 0; u < 8; u++)
#pragma unroll
        for (int v = 0; v < 8; v++) acc[u][v] = 0.f;

    for (int t = 0; t < L_; t++) {
        float k8[8], v8[8];
        *(float4*)(k8)   = *(const float4*)&Ks[t][i0];
        *(float4*)(k8+4) = *(const float4*)&Ks[t][i0+4];
        *(float4*)(v8)   = *(const float4*)&Vs[t][j0];
        *(float4*)(v8+4) = *(const float4*)&Vs[t][j0+4];
#pragma unroll
        for (int u = 0; u < 8; u++)
#pragma unroll
            for (int v = 0; v < 8; v++) acc[u][v] += k8[u]*v8[v];
    }
    float* op = g_Ssum + (((size_t)(b*C_ + c))*D_ + i0)*D_ + j0;
#pragma unroll
    for (int u = 0; u < 8; u++) {
        *(float4*)(op + (size_t)u*D_)     = make_float4(acc[u][0],acc[u][1],acc[u][2],acc[u][3]);
        *(float4*)(op + (size_t)u*D_ + 4) = make_float4(acc[u][4],acc[u][5],acc[u][6],acc[u][7]);
    }
}

// ---------------- k4: fused scan + num/den + FFN + out (k5 eliminated) ----------------
// smem: Ks,Vs,Qs (24KB) + part[2][32][128] (32KB) + numBuf[32][128] (16KB) + dqz[2][128] + sden[32]
#define K4_SMEM ((3*SUB_*D_ + 2*32*D_ + 32*D_ + 2*D_ + 32) * (int)sizeof(float))
__global__ void __launch_bounds__(1024, 1)
k4_main(const float* __restrict__ S0, const float* __restrict__ Z0,
        const float* __restrict__ W1, const float* __restrict__ b1_,
        const float* __restrict__ W2, const float* __restrict__ b2_,
        float* __restrict__ outO, float* __restrict__ outS, float* __restrict__ outZ) {
    const int c = blockIdx.x, b = blockIdx.y;
    const int tid = threadIdx.x;         // 1024
    const int ri = tid >> 5;             // 0..31
    const int jg = tid & 31;             // 0..31
    const int i0 = ri << 2, j0 = jg << 2;

    extern __shared__ float dsm[];
    float* Ks     = dsm;                        // [SUB_][D_]
    float* Vs     = Ks + SUB_*D_;
    float* Qs     = Vs + SUB_*D_;
    float* part   = Qs + SUB_*D_;               // [2][32][D_]
    float* numBuf = part + 2*32*D_;             // [32][D_]
    float* dqz    = numBuf + 32*D_;             // [2][D_]
    float* sden   = dqz + 2*D_;                 // [32]

    // init: S0 + sum of raw chunk sums c' < c
    float s[4][4];
    {
        const float* s0g = S0 + ((size_t)b*D_ + i0)*D_ + j0;
#pragma unroll
        for (int u = 0; u < 4; u++) {
            const float4 z = *(const float4*)(s0g + (size_t)u*D_);
            s[u][0] = z.x; s[u][1] = z.y; s[u][2] = z.z; s[u][3] = z.w;
        }
        for (int c2 = 0; c2 < c; c2++) {
            const float* sp = g_Ssum + ((size_t)(b*C_ + c2)*D_ + i0)*D_ + j0;
#pragma unroll
            for (int u = 0; u < 4; u++) {
                const float4 a = __ldg((const float4*)(sp + (size_t)u*D_));
                s[u][0] += a.x; s[u][1] += a.y; s[u][2] += a.z; s[u][3] += a.w;
            }
        }
    }

    float zrun = 0.f;
    if (tid < D_) {
        zrun = Z0[b*D_ + tid];
        for (int c2 = 0; c2 < c; c2++)
            zrun += g_Zsum[(size_t)(b*C_ + c2)*D_ + tid];
    }

    const int t0 = c * L_;
    for (int sub = 0; sub < L_/SUB_; sub++) {
        const int tg = t0 + sub*SUB_;
        {
            const float4* kg = (const float4*)(g_K + ((size_t)b*T_ + tg)*D_);
            const float4* vg = (const float4*)(g_V + ((size_t)b*T_ + tg)*D_);
            const float4* qg = (const float4*)(g_Q + ((size_t)b*T_ + tg)*D_);
            const int h = tid & 511;
            if (tid < 512) { ((float4*)Ks)[h] = kg[h]; ((float4*)Vs)[h] = vg[h]; }
            else           { ((float4*)Qs)[h] = qg[h]; }
        }
        __syncthreads();

        for (int tt = 0; tt < SUB_; tt++) {
            const int t = tg + tt;
            const int lt = sub*SUB_ + tt;       // 0..31 local row
            const float4 kv = *(const float4*)&Ks[tt*D_ + i0];
            const float4 vv = *(const float4*)&Vs[tt*D_ + j0];
            const float4 qv = *(const float4*)&Qs[tt*D_ + i0];
            const float kk[4] = {kv.x, kv.y, kv.z, kv.w};
            const float vb[4] = {vv.x, vv.y, vv.z, vv.w};
            const float qq[4] = {qv.x, qv.y, qv.z, qv.w};
            float p0 = 0.f, p1 = 0.f, p2 = 0.f, p3 = 0.f;
            float* orow = outS + (((size_t)b*T_ + t)*D_ + i0)*D_ + j0;
#pragma unroll
            for (int u = 0; u < 4; u++) {
                s[u][0] += kk[u]*vb[0];
                s[u][1] += kk[u]*vb[1];
                s[u][2] += kk[u]*vb[2];
                s[u][3] += kk[u]*vb[3];
                __stcs((float4*)(orow + (size_t)u*D_),
                       make_float4(s[u][0], s[u][1], s[u][2], s[u][3]));
                p0 += qq[u]*s[u][0];
                p1 += qq[u]*s[u][1];
                p2 += qq[u]*s[u][2];
                p3 += qq[u]*s[u][3];
            }
            float* pb = part + (tt & 1)*32*D_;
            *(float4*)&pb[ri*D_ + j0] = make_float4(p0, p1, p2, p3);
            if (tid < D_) {
                zrun += Ks[tt*D_ + tid];
                outZ[((size_t)b*T_ + t)*D_ + tid] = zrun;
                dqz[(tt & 1)*D_ + tid] = Qs[tt*D_ + tid] * zrun;   // den partials
            }
            __syncthreads();
            if (tid < D_) {
                float sum = 0.f;
#pragma unroll
                for (int rr = 0; rr < 32; rr++) sum += pb[rr*D_ + tid];
                numBuf[lt*D_ + tid] = sum;
            } else if (tid < 160) {
                // warp 4: reduce dqz -> sden[lt]
                const float* dz = dqz + (tt & 1)*D_;
                const int l = tid - 128;
                float v = dz[l] + dz[l+32] + dz[l+64] + dz[l+96];
#pragma unroll
                for (int off = 16; off; off >>= 1) v += __shfl_xor_sync(0xffffffffu, v, off);
                if (l == 0) sden[lt] = v;
            }
        }
        __syncthreads();
    }

    // ---- FFN tail: warp ri owns local row ri ----
    const int lane = jg;
    const float rden = 1.0f / (sden[ri] + 1e-5f);
    float4 acc;
    {
        acc = __ldg(((const float4*)b1_) + lane);
        const float* nb = numBuf + ri*D_;
        for (int k = 0; k < D_; k++) {
            const float a = nb[k] * rden;
            const float4 wv = __ldg(((const float4*)(W1 + (size_t)k*D_)) + lane);
            acc.x += a*wv.x; acc.y += a*wv.y; acc.z += a*wv.z; acc.w += a*wv.w;
        }
        // h row into part (reuse)
        ((float4*)part)[ri*32 + lane] = make_float4(fmaxf(acc.x,0.f), fmaxf(acc.y,0.f),
                                                    fmaxf(acc.z,0.f), fmaxf(acc.w,0.f));
    }
    __syncwarp();
    {
        acc = __ldg(((const float4*)b2_) + lane);
        const float* hb = part + ri*D_;
        for (int k = 0; k < D_; k++) {
            const float h = hb[k];
            const float4 wv = __ldg(((const float4*)(W2 + (size_t)k*D_)) + lane);
            acc.x += h*wv.x; acc.y += h*wv.y; acc.z += h*wv.z; acc.w += h*wv.w;
        }
        const size_t row = (size_t)b*T_ + c*L_ + ri;
        const float4 rv = *(const float4*)(g_R + row*D_ + j0);
        float4 o;
        o.x = fmaxf(acc.x, 0.f) + rv.x;
        o.y = fmaxf(acc.y, 0.f) + rv.y;
        o.z = fmaxf(acc.z, 0.f) + rv.z;
        o.w = fmaxf(acc.w, 0.f) + rv.w;
        *(float4*)(outO + row*D_ + j0) = o;
    }
}

// ---------------- launch ----------------
extern "C" void kernel_launch(void* const* d_in, const int* in_sizes, int n_in,
                              void* d_out, int out_size) {
    const float* x     = (const float*)d_in[0];
    const float* S0    = (const float*)d_in[1];
    const float* Z0    = (const float*)d_in[2];
    const float* gamma = (const float*)d_in[3];
    const float* beta  = (const float*)d_in[4];
    const float* Wk    = (const float*)d_in[5];
    const float* Wq    = (const float*)d_in[6];
    const float* Wv    = (const float*)d_in[7];
    const float* W1    = (const float*)d_in[8];
    const float* b1    = (const float*)d_in[9];
    const float* W2    = (const float*)d_in[10];
    const float* b2    = (const float*)d_in[11];
    const float* Ws    = (const float*)d_in[12];
    const float* bs    = (const float*)d_in[13];

    float* outO = (float*)d_out;
    float* outS = outO + (size_t)B_*T_*D_;
    float* outZ = outS + (size_t)B_*T_*D_*D_;

    static bool attr_done = false;
    if (!attr_done) {
        cudaFuncSetAttribute(k4_main, cudaFuncAttributeMaxDynamicSharedMemorySize, K4_SMEM);
        cudaFuncSetAttribute(k1_tf32, cudaFuncAttributeMaxDynamicSharedMemorySize, K1_SMEM);
        attr_done = true;
    }

    k0_ln<<<(B_*T_)/32, 256>>>(x, gamma, beta);
    k1_tf32<<<dim3((B_*T_)/64, 4), 256, K1_SMEM>>>(Wk, Wq, Wv, Ws, bs);
    k2_chunksum<<<dim3(C_, B_), 256>>>();
    k4_main<<<dim3(C_, B_), 1024, K4_SMEM>>>(S0, Z0, W1, b1, W2, b2, outO, outS, outZ);
}

// round 13
// speedup vs baseline: 1.0153x; 1.0153x over previous
#include <cuda_runtime.h>
#include <math.h>
#include <stdint.h>

#define B_   8
#define T_   512
#define FIN_ 256
#define D_   128
#define C_   16          // chunks per batch
#define L_   32          // chunk length (T_/C_)
#define SUB_ 16          // sub-tile of timesteps in k4 smem

// ---------------- scratch ----------------
__device__ __align__(16) float g_XN[B_*T_*FIN_];
__device__ __align__(16) float g_K[B_*T_*D_];
__device__ __align__(16) float g_Q[B_*T_*D_];
__device__ __align__(16) float g_V[B_*T_*D_];
__device__ __align__(16) float g_R[B_*T_*D_];
__device__ __align__(16) float g_Ssum[B_*C_*D_*D_];  // RAW per-chunk outer sums
__device__ __align__(16) float g_Zsum[B_*C_*D_];     // RAW per-chunk K sums

// ---------------- tf32 helpers ----------------
__device__ __forceinline__ uint32_t f2tf32(float x) {
    uint32_t r; asm("cvt.rna.tf32.f32 %0, %1;" : "=r"(r) : "f"(x)); return r;
}
__device__ __forceinline__ void mma_tf32(float* d, const uint32_t* a, const uint32_t* b) {
    asm volatile(
        "mma.sync.aligned.m16n8k8.row.col.f32.tf32.tf32.f32 "
        "{%0,%1,%2,%3}, {%4,%5,%6,%7}, {%8,%9}, {%0,%1,%2,%3};"
        : "+f"(d[0]), "+f"(d[1]), "+f"(d[2]), "+f"(d[3])
        : "r"(a[0]), "r"(a[1]), "r"(a[2]), "r"(a[3]), "r"(b[0]), "r"(b[1]));
}

// ---------------- k0: LayerNorm -> g_XN ----------------
__global__ void k0_ln(const float* __restrict__ x,
                      const float* __restrict__ gamma, const float* __restrict__ beta) {
    const int tid  = threadIdx.x;
    const int w    = tid >> 5, lane = tid & 31;
    const int row0 = blockIdx.x * 32;

    float gv[8], bv[8];
#pragma unroll
    for (int k = 0; k < 8; k++) { gv[k] = gamma[lane + 32*k]; bv[k] = beta[lane + 32*k]; }

#pragma unroll
    for (int rr = 0; rr < 4; rr++) {
        const size_t r = (size_t)row0 + w*4 + rr;
        float s = 0.f, ss = 0.f, xv[8];
#pragma unroll
        for (int k = 0; k < 8; k++) {
            float v = x[r*FIN_ + lane + 32*k];
            xv[k] = v; s += v; ss += v*v;
        }
#pragma unroll
        for (int off = 16; off; off >>= 1) {
            s  += __shfl_xor_sync(0xffffffffu, s,  off);
            ss += __shfl_xor_sync(0xffffffffu, ss, off);
        }
        const float mu   = s * (1.0f/FIN_);
        const float rstd = rsqrtf(ss*(1.0f/FIN_) - mu*mu + 1e-5f);
#pragma unroll
        for (int k = 0; k < 8; k++)
            g_XN[r*FIN_ + lane + 32*k] = (xv[k]-mu)*rstd*gv[k] + bv[k];
    }
}

// ---------------- k1: tf32 tensor-core projections, 3xTF32 split ----------------
#define XP 36
#define WP 132
#define K1_SMEM ((2*64*XP + 2*32*WP) * 4)   // 52224 B
__global__ void __launch_bounds__(256)
k1_tf32(const float* __restrict__ Wk, const float* __restrict__ Wq,
        const float* __restrict__ Wv, const float* __restrict__ Ws,
        const float* __restrict__ bs) {
    extern __shared__ uint32_t su[];
    uint32_t* xh = su;
    uint32_t* xl = xh + 64*XP;
    uint32_t* wh = xl + 64*XP;
    uint32_t* wl = wh + 32*WP;

    const int tid  = threadIdx.x;
    const int lane = tid & 31;
    const int wid  = tid >> 5;
    const int wm   = wid >> 1;
    const int wn   = wid & 1;
    const int g    = lane >> 2;
    const int t    = lane & 3;
    const int row0 = blockIdx.x * 64;
    const int m    = blockIdx.y;

    const float* Wp = (m==0) ? Wk : (m==1) ? Wq : (m==2) ? Wv : Ws;
    float*       Op = (m==0) ? g_K : (m==1) ? g_Q : (m==2) ? g_V : g_R;

    float d[8][4];
#pragma unroll
    for (int nt = 0; nt < 8; nt++)
#pragma unroll
        for (int q = 0; q < 4; q++) d[nt][q] = 0.f;

    for (int kc = 0; kc < FIN_; kc += 32) {
        __syncthreads();
#pragma unroll
        for (int p = 0; p < 2; p++) {
            const int idx = p*256 + tid;
            const int r = idx >> 3, c4 = (idx & 7) * 4;
            const float4 v = *(const float4*)(g_XN + ((size_t)row0 + r)*FIN_ + kc + c4);
            uint4 h, l;
            h.x = f2tf32(v.x); l.x = f2tf32(v.x - __uint_as_float(h.x));
            h.y = f2tf32(v.y); l.y = f2tf32(v.y - __uint_as_float(h.y));
            h.z = f2tf32(v.z); l.z = f2tf32(v.z - __uint_as_float(h.z));
            h.w = f2tf32(v.w); l.w = f2tf32(v.w - __uint_as_float(h.w));
            *(uint4*)&xh[r*XP + c4] = h;
            *(uint4*)&xl[r*XP + c4] = l;
        }
#pragma unroll
        for (int p = 0; p < 4; p++) {
            const int idx = p*256 + tid;
            const int r = idx >> 5, c4 = (idx & 31) * 4;
            const float4 v = *(const float4*)(Wp + ((size_t)kc + r)*D_ + c4);
            uint4 h, l;
            h.x = f2tf32(v.x); l.x = f2tf32(v.x - __uint_as_float(h.x));
            h.y = f2tf32(v.y); l.y = f2tf32(v.y - __uint_as_float(h.y));
            h.z = f2tf32(v.z); l.z = f2tf32(v.z - __uint_as_float(h.z));
            h.w = f2tf32(v.w); l.w = f2tf32(v.w - __uint_as_float(h.w));
            *(uint4*)&wh[r*WP + c4] = h;
            *(uint4*)&wl[r*WP + c4] = l;
        }
        __syncthreads();

#pragma unroll
        for (int ks = 0; ks < 4; ks++) {
            const int ko = ks * 8;
            const int m0 = wm * 16;
            uint32_t ah[4], al[4];
            ah[0] = xh[(m0+g)*XP   + ko + t];
            ah[1] = xh[(m0+g+8)*XP + ko + t];
            ah[2] = xh[(m0+g)*XP   + ko + t + 4];
            ah[3] = xh[(m0+g+8)*XP + ko + t + 4];
            al[0] = xl[(m0+g)*XP   + ko + t];
            al[1] = xl[(m0+g+8)*XP + ko + t];
            al[2] = xl[(m0+g)*XP   + ko + t + 4];
            al[3] = xl[(m0+g+8)*XP + ko + t + 4];
#pragma unroll
            for (int nt = 0; nt < 8; nt++) {
                const int n0 = wn*64 + nt*8;
                uint32_t bh[2], bl[2];
                bh[0] = wh[(ko+t)*WP   + n0 + g];
                bh[1] = wh[(ko+t+4)*WP + n0 + g];
                bl[0] = wl[(ko+t)*WP   + n0 + g];
                bl[1] = wl[(ko+t+4)*WP + n0 + g];
                mma_tf32(d[nt], ah, bh);
                mma_tf32(d[nt], ah, bl);
                mma_tf32(d[nt], al, bh);
            }
        }
    }

#pragma unroll
    for (int nt = 0; nt < 8; nt++) {
        const int n0 = wn*64 + nt*8;
        const int cA = n0 + t*2;
        float v0 = d[nt][0], v1 = d[nt][1], v2 = d[nt][2], v3 = d[nt][3];
        if (m <= 1) {
            v0 = (v0 > 0.f) ? (v0 + 1.f) : expf(v0);
            v1 = (v1 > 0.f) ? (v1 + 1.f) : expf(v1);
            v2 = (v2 > 0.f) ? (v2 + 1.f) : expf(v2);
            v3 = (v3 > 0.f) ? (v3 + 1.f) : expf(v3);
        } else if (m == 3) {
            const float b0 = bs[cA], b1 = bs[cA+1];
            v0 += b0; v1 += b1; v2 += b0; v3 += b1;
        }
        const size_t r0 = (size_t)row0 + wm*16 + g;
        *(float2*)(Op + r0*D_ + cA)       = make_float2(v0, v1);
        *(float2*)(Op + (r0+8)*D_ + cA)   = make_float2(v2, v3);
    }
}

// ---------------- k2: per-chunk outer-product sums + K sums (RAW) ----------------
__global__ void k2_chunksum() {
    const int c = blockIdx.x, b = blockIdx.y;
    const int tid = threadIdx.x;   // 256
    __shared__ __align__(16) float Ks[L_][D_];
    __shared__ __align__(16) float Vs[L_][D_];
    {
        const float4* kg = (const float4*)(g_K + ((size_t)b*T_ + c*L_)*D_);
        const float4* vg = (const float4*)(g_V + ((size_t)b*T_ + c*L_)*D_);
        for (int q = tid; q < L_*D_/4; q += 256) { ((float4*)Ks)[q] = kg[q]; ((float4*)Vs)[q] = vg[q]; }
    }
    __syncthreads();

    if (tid < D_) {
        float zs = 0.f;
#pragma unroll
        for (int t = 0; t < L_; t++) zs += Ks[t][tid];
        g_Zsum[((size_t)(b*C_ + c))*D_ + tid] = zs;
    }

    const int tr = tid >> 4, tc = tid & 15;
    const int i0 = tr*8, j0 = tc*8;
    float acc[8][8];
#pragma unroll
    for (int u = 0; u < 8; u++)
#pragma unroll
        for (int v = 0; v < 8; v++) acc[u][v] = 0.f;

    for (int t = 0; t < L_; t++) {
        float k8[8], v8[8];
        *(float4*)(k8)   = *(const float4*)&Ks[t][i0];
        *(float4*)(k8+4) = *(const float4*)&Ks[t][i0+4];
        *(float4*)(v8)   = *(const float4*)&Vs[t][j0];
        *(float4*)(v8+4) = *(const float4*)&Vs[t][j0+4];
#pragma unroll
        for (int u = 0; u < 8; u++)
#pragma unroll
            for (int v = 0; v < 8; v++) acc[u][v] += k8[u]*v8[v];
    }
    float* op = g_Ssum + (((size_t)(b*C_ + c))*D_ + i0)*D_ + j0;
#pragma unroll
    for (int u = 0; u < 8; u++) {
        *(float4*)(op + (size_t)u*D_)     = make_float4(acc[u][0],acc[u][1],acc[u][2],acc[u][3]);
        *(float4*)(op + (size_t)u*D_ + 4) = make_float4(acc[u][4],acc[u][5],acc[u][6],acc[u][7]);
    }
}

// ---------------- k4: fused scan + num (smem) + den/FFN tail (smem-tiled) ----------------
// smem: Ks,Vs,Qs (24KB) + part[2][32][128] (32KB, reused as wbuf/hbuf) + numBuf[32][128] (16KB)
#define K4_SMEM ((3*SUB_*D_ + 2*32*D_ + 32*D_) * (int)sizeof(float))   // 73728
__global__ void __launch_bounds__(1024, 1)
k4_main(const float* __restrict__ S0, const float* __restrict__ Z0,
        const float* __restrict__ W1, const float* __restrict__ b1_,
        const float* __restrict__ W2, const float* __restrict__ b2_,
        float* __restrict__ outO, float* __restrict__ outS, float* __restrict__ outZ) {
    const int c = blockIdx.x, b = blockIdx.y;
    const int tid = threadIdx.x;         // 1024
    const int ri = tid >> 5;             // 0..31
    const int jg = tid & 31;             // 0..31
    const int i0 = ri << 2, j0 = jg << 2;

    extern __shared__ float dsm[];
    float* Ks     = dsm;                        // [SUB_][D_]
    float* Vs     = Ks + SUB_*D_;
    float* Qs     = Vs + SUB_*D_;
    float* part   = Qs + SUB_*D_;               // [2][32][D_] — scan partials; tail: wbuf+hbuf
    float* numBuf = part + 2*32*D_;             // [32][D_]

    // init: S0 + sum of raw chunk sums c' < c
    float s[4][4];
    {
        const float* s0g = S0 + ((size_t)b*D_ + i0)*D_ + j0;
#pragma unroll
        for (int u = 0; u < 4; u++) {
            const float4 z = *(const float4*)(s0g + (size_t)u*D_);
            s[u][0] = z.x; s[u][1] = z.y; s[u][2] = z.z; s[u][3] = z.w;
        }
        for (int c2 = 0; c2 < c; c2++) {
            const float* sp = g_Ssum + ((size_t)(b*C_ + c2)*D_ + i0)*D_ + j0;
#pragma unroll
            for (int u = 0; u < 4; u++) {
                const float4 a = __ldg((const float4*)(sp + (size_t)u*D_));
                s[u][0] += a.x; s[u][1] += a.y; s[u][2] += a.z; s[u][3] += a.w;
            }
        }
    }

    float zrun = 0.f;
    if (tid < D_) {
        zrun = Z0[b*D_ + tid];
        for (int c2 = 0; c2 < c; c2++)
            zrun += g_Zsum[(size_t)(b*C_ + c2)*D_ + tid];
    }

    const int t0 = c * L_;
    for (int sub = 0; sub < L_/SUB_; sub++) {
        const int tg = t0 + sub*SUB_;
        {
            const float4* kg = (const float4*)(g_K + ((size_t)b*T_ + tg)*D_);
            const float4* vg = (const float4*)(g_V + ((size_t)b*T_ + tg)*D_);
            const float4* qg = (const float4*)(g_Q + ((size_t)b*T_ + tg)*D_);
            const int h = tid & 511;
            if (tid < 512) { ((float4*)Ks)[h] = kg[h]; ((float4*)Vs)[h] = vg[h]; }
            else           { ((float4*)Qs)[h] = qg[h]; }
        }
        __syncthreads();

        for (int tt = 0; tt < SUB_; tt++) {
            const int t = tg + tt;
            const int lt = sub*SUB_ + tt;       // 0..31 local row
            const float4 kv = *(const float4*)&Ks[tt*D_ + i0];
            const float4 vv = *(const float4*)&Vs[tt*D_ + j0];
            const float4 qv = *(const float4*)&Qs[tt*D_ + i0];
            const float kk[4] = {kv.x, kv.y, kv.z, kv.w};
            const float vb[4] = {vv.x, vv.y, vv.z, vv.w};
            const float qq[4] = {qv.x, qv.y, qv.z, qv.w};
            float p0 = 0.f, p1 = 0.f, p2 = 0.f, p3 = 0.f;
            float* orow = outS + (((size_t)b*T_ + t)*D_ + i0)*D_ + j0;
#pragma unroll
            for (int u = 0; u < 4; u++) {
                s[u][0] += kk[u]*vb[0];
                s[u][1] += kk[u]*vb[1];
                s[u][2] += kk[u]*vb[2];
                s[u][3] += kk[u]*vb[3];
                __stcs((float4*)(orow + (size_t)u*D_),
                       make_float4(s[u][0], s[u][1], s[u][2], s[u][3]));
                p0 += qq[u]*s[u][0];
                p1 += qq[u]*s[u][1];
                p2 += qq[u]*s[u][2];
                p3 += qq[u]*s[u][3];
            }
            float* pb = part + (tt & 1)*32*D_;
            *(float4*)&pb[ri*D_ + j0] = make_float4(p0, p1, p2, p3);
            if (tid < D_) {
                zrun += Ks[tt*D_ + tid];
                outZ[((size_t)b*T_ + t)*D_ + tid] = zrun;
            }
            __syncthreads();
            if (tid < D_) {
                float sum = 0.f;
#pragma unroll
                for (int rr = 0; rr < 32; rr++) sum += pb[rr*D_ + tid];
                numBuf[lt*D_ + tid] = sum;
            }
        }
        __syncthreads();
    }

    // ---- tail: den per warp (Q, Z re-read from L2), a = num/den in place ----
    {
        const size_t row = (size_t)b*T_ + c*L_ + ri;
        const float4 q4 = __ldg((const float4*)(g_Q + row*D_) + jg);
        const float4 z4 = *((const float4*)(outZ + row*D_) + jg);
        float dv = q4.x*z4.x + q4.y*z4.y + q4.z*z4.z + q4.w*z4.w;
#pragma unroll
        for (int off = 16; off; off >>= 1) dv += __shfl_xor_sync(0xffffffffu, dv, off);
        const float rden = 1.0f / (dv + 1e-5f);
        float4 nv = *(float4*)&numBuf[ri*D_ + j0];
        nv.x *= rden; nv.y *= rden; nv.z *= rden; nv.w *= rden;
        *(float4*)&numBuf[ri*D_ + j0] = nv;
    }

    // ---- FFN: smem-tiled; wbuf = part[0:16KB], hbuf = part[16KB:32KB] ----
    float* wbuf = part;
    float* hbuf = part + 32*D_;
    const int sr = tid >> 5;        // stage row 0..31
    const int sc = tid & 31;        // stage col-quad 0..31

    float4 acc = __ldg((const float4*)b1_ + jg);
    for (int kc = 0; kc < D_; kc += 32) {
        __syncthreads();
        *(float4*)&wbuf[sr*D_ + sc*4] =
            __ldg((const float4*)(W1 + (size_t)(kc + sr)*D_) + sc);
        __syncthreads();
#pragma unroll
        for (int k = 0; k < 32; k++) {
            const float a = numBuf[ri*D_ + kc + k];
            const float4 wv = *(const float4*)&wbuf[k*D_ + j0];
            acc.x += a*wv.x; acc.y += a*wv.y; acc.z += a*wv.z; acc.w += a*wv.w;
        }
    }
    __syncthreads();
    *(float4*)&hbuf[ri*D_ + j0] = make_float4(fmaxf(acc.x,0.f), fmaxf(acc.y,0.f),
                                              fmaxf(acc.z,0.f), fmaxf(acc.w,0.f));

    acc = __ldg((const float4*)b2_ + jg);
    for (int kc = 0; kc < D_; kc += 32) {
        __syncthreads();
        *(float4*)&wbuf[sr*D_ + sc*4] =
            __ldg((const float4*)(W2 + (size_t)(kc + sr)*D_) + sc);
        __syncthreads();
#pragma unroll
        for (int k = 0; k < 32; k++) {
            const float h = hbuf[ri*D_ + kc + k];
            const float4 wv = *(const float4*)&wbuf[k*D_ + j0];
            acc.x += h*wv.x; acc.y += h*wv.y; acc.z += h*wv.z; acc.w += h*wv.w;
        }
    }
    {
        const size_t row = (size_t)b*T_ + c*L_ + ri;
        const float4 rv = *(const float4*)(g_R + row*D_ + j0);
        float4 o;
        o.x = fmaxf(acc.x, 0.f) + rv.x;
        o.y = fmaxf(acc.y, 0.f) + rv.y;
        o.z = fmaxf(acc.z, 0.f) + rv.z;
        o.w = fmaxf(acc.w, 0.f) + rv.w;
        *(float4*)(outO + row*D_ + j0) = o;
    }
}

// ---------------- launch ----------------
extern "C" void kernel_launch(void* const* d_in, const int* in_sizes, int n_in,
                              void* d_out, int out_size) {
    const float* x     = (const float*)d_in[0];
    const float* S0    = (const float*)d_in[1];
    const float* Z0    = (const float*)d_in[2];
    const float* gamma = (const float*)d_in[3];
    const float* beta  = (const float*)d_in[4];
    const float* Wk    = (const float*)d_in[5];
    const float* Wq    = (const float*)d_in[6];
    const float* Wv    = (const float*)d_in[7];
    const float* W1    = (const float*)d_in[8];
    const float* b1    = (const float*)d_in[9];
    const float* W2    = (const float*)d_in[10];
    const float* b2    = (const float*)d_in[11];
    const float* Ws    = (const float*)d_in[12];
    const float* bs    = (const float*)d_in[13];

    float* outO = (float*)d_out;
    float* outS = outO + (size_t)B_*T_*D_;
    float* outZ = outS + (size_t)B_*T_*D_*D_;

    static bool attr_done = false;
    if (!attr_done) {
        cudaFuncSetAttribute(k4_main, cudaFuncAttributeMaxDynamicSharedMemorySize, K4_SMEM);
        cudaFuncSetAttribute(k1_tf32, cudaFuncAttributeMaxDynamicSharedMemorySize, K1_SMEM);
        attr_done = true;
    }

    k0_ln<<<(B_*T_)/32, 256>>>(x, gamma, beta);
    k1_tf32<<<dim3((B_*T_)/64, 4), 256, K1_SMEM>>>(Wk, Wq, Wv, Ws, bs);
    k2_chunksum<<<dim3(C_, B_), 256>>>();
    k4_main<<<dim3(C_, B_), 1024, K4_SMEM>>>(S0, Z0, W1, b1, W2, b2, outO, outS, outZ);
}

// round 14
// speedup vs baseline: 1.0981x; 1.0816x over previous
#include <cuda_runtime.h>
#include <math.h>
#include <stdint.h>

#define B_   8
#define T_   512
#define FIN_ 256
#define D_   128
#define C_   16          // chunks per batch
#define L_   32          // chunk length (T_/C_)
#define SUB_ 16          // sub-tile of timesteps in k4 smem

// ---------------- scratch ----------------
__device__ __align__(16) float g_XN[B_*T_*FIN_];
__device__ __align__(16) float g_K[B_*T_*D_];
__device__ __align__(16) float g_Q[B_*T_*D_];
__device__ __align__(16) float g_V[B_*T_*D_];
__device__ __align__(16) float g_R[B_*T_*D_];
__device__ __align__(16) float g_Ssum[B_*C_*D_*D_];  // RAW per-chunk outer sums
__device__ __align__(16) float g_Zsum[B_*C_*D_];     // RAW per-chunk K sums

// ---------------- tf32 helpers ----------------
__device__ __forceinline__ uint32_t f2tf32(float x) {
    uint32_t r; asm("cvt.rna.tf32.f32 %0, %1;" : "=r"(r) : "f"(x)); return r;
}
__device__ __forceinline__ void mma_tf32(float* d, const uint32_t* a, const uint32_t* b) {
    asm volatile(
        "mma.sync.aligned.m16n8k8.row.col.f32.tf32.tf32.f32 "
        "{%0,%1,%2,%3}, {%4,%5,%6,%7}, {%8,%9}, {%0,%1,%2,%3};"
        : "+f"(d[0]), "+f"(d[1]), "+f"(d[2]), "+f"(d[3])
        : "r"(a[0]), "r"(a[1]), "r"(a[2]), "r"(a[3]), "r"(b[0]), "r"(b[1]));
}

// ---------------- k0: LayerNorm -> g_XN ----------------
__global__ void k0_ln(const float* __restrict__ x,
                      const float* __restrict__ gamma, const float* __restrict__ beta) {
    const int tid  = threadIdx.x;
    const int w    = tid >> 5, lane = tid & 31;
    const int row0 = blockIdx.x * 32;

    float gv[8], bv[8];
#pragma unroll
    for (int k = 0; k < 8; k++) { gv[k] = gamma[lane + 32*k]; bv[k] = beta[lane + 32*k]; }

#pragma unroll
    for (int rr = 0; rr < 4; rr++) {
        const size_t r = (size_t)row0 + w*4 + rr;
        float s = 0.f, ss = 0.f, xv[8];
#pragma unroll
        for (int k = 0; k < 8; k++) {
            float v = x[r*FIN_ + lane + 32*k];
            xv[k] = v; s += v; ss += v*v;
        }
#pragma unroll
        for (int off = 16; off; off >>= 1) {
            s  += __shfl_xor_sync(0xffffffffu, s,  off);
            ss += __shfl_xor_sync(0xffffffffu, ss, off);
        }
        const float mu   = s * (1.0f/FIN_);
        const float rstd = rsqrtf(ss*(1.0f/FIN_) - mu*mu + 1e-5f);
#pragma unroll
        for (int k = 0; k < 8; k++)
            g_XN[r*FIN_ + lane + 32*k] = (xv[k]-mu)*rstd*gv[k] + bv[k];
    }
}

// ---------------- k1: tf32 tensor-core projections, 3xTF32 split ----------------
#define XP 36
#define WP 132
#define K1_SMEM ((2*64*XP + 2*32*WP) * 4)   // 52224 B
__global__ void __launch_bounds__(256)
k1_tf32(const float* __restrict__ Wk, const float* __restrict__ Wq,
        const float* __restrict__ Wv, const float* __restrict__ Ws,
        const float* __restrict__ bs) {
    extern __shared__ uint32_t su[];
    uint32_t* xh = su;
    uint32_t* xl = xh + 64*XP;
    uint32_t* wh = xl + 64*XP;
    uint32_t* wl = wh + 32*WP;

    const int tid  = threadIdx.x;
    const int lane = tid & 31;
    const int wid  = tid >> 5;
    const int wm   = wid >> 1;
    const int wn   = wid & 1;
    const int g    = lane >> 2;
    const int t    = lane & 3;
    const int row0 = blockIdx.x * 64;
    const int m    = blockIdx.y;

    const float* Wp = (m==0) ? Wk : (m==1) ? Wq : (m==2) ? Wv : Ws;
    float*       Op = (m==0) ? g_K : (m==1) ? g_Q : (m==2) ? g_V : g_R;

    float d[8][4];
#pragma unroll
    for (int nt = 0; nt < 8; nt++)
#pragma unroll
        for (int q = 0; q < 4; q++) d[nt][q] = 0.f;

    for (int kc = 0; kc < FIN_; kc += 32) {
        __syncthreads();
#pragma unroll
        for (int p = 0; p < 2; p++) {
            const int idx = p*256 + tid;
            const int r = idx >> 3, c4 = (idx & 7) * 4;
            const float4 v = *(const float4*)(g_XN + ((size_t)row0 + r)*FIN_ + kc + c4);
            uint4 h, l;
            h.x = f2tf32(v.x); l.x = f2tf32(v.x - __uint_as_float(h.x));
            h.y = f2tf32(v.y); l.y = f2tf32(v.y - __uint_as_float(h.y));
            h.z = f2tf32(v.z); l.z = f2tf32(v.z - __uint_as_float(h.z));
            h.w = f2tf32(v.w); l.w = f2tf32(v.w - __uint_as_float(h.w));
            *(uint4*)&xh[r*XP + c4] = h;
            *(uint4*)&xl[r*XP + c4] = l;
        }
#pragma unroll
        for (int p = 0; p < 4; p++) {
            const int idx = p*256 + tid;
            const int r = idx >> 5, c4 = (idx & 31) * 4;
            const float4 v = *(const float4*)(Wp + ((size_t)kc + r)*D_ + c4);
            uint4 h, l;
            h.x = f2tf32(v.x); l.x = f2tf32(v.x - __uint_as_float(h.x));
            h.y = f2tf32(v.y); l.y = f2tf32(v.y - __uint_as_float(h.y));
            h.z = f2tf32(v.z); l.z = f2tf32(v.z - __uint_as_float(h.z));
            h.w = f2tf32(v.w); l.w = f2tf32(v.w - __uint_as_float(h.w));
            *(uint4*)&wh[r*WP + c4] = h;
            *(uint4*)&wl[r*WP + c4] = l;
        }
        __syncthreads();

#pragma unroll
        for (int ks = 0; ks < 4; ks++) {
            const int ko = ks * 8;
            const int m0 = wm * 16;
            uint32_t ah[4], al[4];
            ah[0] = xh[(m0+g)*XP   + ko + t];
            ah[1] = xh[(m0+g+8)*XP + ko + t];
            ah[2] = xh[(m0+g)*XP   + ko + t + 4];
            ah[3] = xh[(m0+g+8)*XP + ko + t + 4];
            al[0] = xl[(m0+g)*XP   + ko + t];
            al[1] = xl[(m0+g+8)*XP + ko + t];
            al[2] = xl[(m0+g)*XP   + ko + t + 4];
            al[3] = xl[(m0+g+8)*XP + ko + t + 4];
#pragma unroll
            for (int nt = 0; nt < 8; nt++) {
                const int n0 = wn*64 + nt*8;
                uint32_t bh[2], bl[2];
                bh[0] = wh[(ko+t)*WP   + n0 + g];
                bh[1] = wh[(ko+t+4)*WP + n0 + g];
                bl[0] = wl[(ko+t)*WP   + n0 + g];
                bl[1] = wl[(ko+t+4)*WP + n0 + g];
                mma_tf32(d[nt], ah, bh);
                mma_tf32(d[nt], ah, bl);
                mma_tf32(d[nt], al, bh);
            }
        }
    }

#pragma unroll
    for (int nt = 0; nt < 8; nt++) {
        const int n0 = wn*64 + nt*8;
        const int cA = n0 + t*2;
        float v0 = d[nt][0], v1 = d[nt][1], v2 = d[nt][2], v3 = d[nt][3];
        if (m <= 1) {
            v0 = (v0 > 0.f) ? (v0 + 1.f) : expf(v0);
            v1 = (v1 > 0.f) ? (v1 + 1.f) : expf(v1);
            v2 = (v2 > 0.f) ? (v2 + 1.f) : expf(v2);
            v3 = (v3 > 0.f) ? (v3 + 1.f) : expf(v3);
        } else if (m == 3) {
            const float b0 = bs[cA], b1 = bs[cA+1];
            v0 += b0; v1 += b1; v2 += b0; v3 += b1;
        }
        const size_t r0 = (size_t)row0 + wm*16 + g;
        *(float2*)(Op + r0*D_ + cA)       = make_float2(v0, v1);
        *(float2*)(Op + (r0+8)*D_ + cA)   = make_float2(v2, v3);
    }
}

// ---------------- k2: per-chunk outer-product sums + K sums (RAW) ----------------
__global__ void k2_chunksum() {
    const int c = blockIdx.x, b = blockIdx.y;
    const int tid = threadIdx.x;   // 256
    __shared__ __align__(16) float Ks[L_][D_];
    __shared__ __align__(16) float Vs[L_][D_];
    {
        const float4* kg = (const float4*)(g_K + ((size_t)b*T_ + c*L_)*D_);
        const float4* vg = (const float4*)(g_V + ((size_t)b*T_ + c*L_)*D_);
        for (int q = tid; q < L_*D_/4; q += 256) { ((float4*)Ks)[q] = kg[q]; ((float4*)Vs)[q] = vg[q]; }
    }
    __syncthreads();

    if (tid < D_) {
        float zs = 0.f;
#pragma unroll
        for (int t = 0; t < L_; t++) zs += Ks[t][tid];
        g_Zsum[((size_t)(b*C_ + c))*D_ + tid] = zs;
    }

    const int tr = tid >> 4, tc = tid & 15;
    const int i0 = tr*8, j0 = tc*8;
    float acc[8][8];
#pragma unroll
    for (int u = 0; u < 8; u++)
#pragma unroll
        for (int v = 0; v < 8; v++) acc[u][v] = 0.f;

    for (int t = 0; t < L_; t++) {
        float k8[8], v8[8];
        *(float4*)(k8)   = *(const float4*)&Ks[t][i0];
        *(float4*)(k8+4) = *(const float4*)&Ks[t][i0+4];
        *(float4*)(v8)   = *(const float4*)&Vs[t][j0];
        *(float4*)(v8+4) = *(const float4*)&Vs[t][j0+4];
#pragma unroll
        for (int u = 0; u < 8; u++)
#pragma unroll
            for (int v = 0; v < 8; v++) acc[u][v] += k8[u]*v8[v];
    }
    float* op = g_Ssum + (((size_t)(b*C_ + c))*D_ + i0)*D_ + j0;
#pragma unroll
    for (int u = 0; u < 8; u++) {
        *(float4*)(op + (size_t)u*D_)     = make_float4(acc[u][0],acc[u][1],acc[u][2],acc[u][3]);
        *(float4*)(op + (size_t)u*D_ + 4) = make_float4(acc[u][4],acc[u][5],acc[u][6],acc[u][7]);
    }
}

// ---------------- k4: fused scan + num (smem) + den + FFN tail (k5 4x4 mapping) ----------------
// smem: Ks,Vs,Qs (24KB) + part[2][32][128] (32KB, tail reuse: wbuf+hbuf) + numBuf[32][128] (16KB)
#define K4_SMEM ((3*SUB_*D_ + 2*32*D_ + 32*D_) * (int)sizeof(float))   // 73728
__global__ void __launch_bounds__(1024, 1)
k4_main(const float* __restrict__ S0, const float* __restrict__ Z0,
        const float* __restrict__ W1, const float* __restrict__ b1_,
        const float* __restrict__ W2, const float* __restrict__ b2_,
        float* __restrict__ outO, float* __restrict__ outS, float* __restrict__ outZ) {
    const int c = blockIdx.x, b = blockIdx.y;
    const int tid = threadIdx.x;         // 1024
    const int ri = tid >> 5;             // 0..31
    const int jg = tid & 31;             // 0..31
    const int i0 = ri << 2, j0 = jg << 2;

    extern __shared__ float dsm[];
    float* Ks     = dsm;                        // [SUB_][D_]
    float* Vs     = Ks + SUB_*D_;
    float* Qs     = Vs + SUB_*D_;
    float* part   = Qs + SUB_*D_;               // [2][32][D_] — scan partials; tail: wbuf+hbuf
    float* numBuf = part + 2*32*D_;             // [32][D_]

    // init: S0 + sum of raw chunk sums c' < c
    float s[4][4];
    {
        const float* s0g = S0 + ((size_t)b*D_ + i0)*D_ + j0;
#pragma unroll
        for (int u = 0; u < 4; u++) {
            const float4 z = *(const float4*)(s0g + (size_t)u*D_);
            s[u][0] = z.x; s[u][1] = z.y; s[u][2] = z.z; s[u][3] = z.w;
        }
        for (int c2 = 0; c2 < c; c2++) {
            const float* sp = g_Ssum + ((size_t)(b*C_ + c2)*D_ + i0)*D_ + j0;
#pragma unroll
            for (int u = 0; u < 4; u++) {
                const float4 a = __ldg((const float4*)(sp + (size_t)u*D_));
                s[u][0] += a.x; s[u][1] += a.y; s[u][2] += a.z; s[u][3] += a.w;
            }
        }
    }

    float zrun = 0.f;
    if (tid < D_) {
        zrun = Z0[b*D_ + tid];
        for (int c2 = 0; c2 < c; c2++)
            zrun += g_Zsum[(size_t)(b*C_ + c2)*D_ + tid];
    }

    const int t0 = c * L_;
    for (int sub = 0; sub < L_/SUB_; sub++) {
        const int tg = t0 + sub*SUB_;
        {
            const float4* kg = (const float4*)(g_K + ((size_t)b*T_ + tg)*D_);
            const float4* vg = (const float4*)(g_V + ((size_t)b*T_ + tg)*D_);
            const float4* qg = (const float4*)(g_Q + ((size_t)b*T_ + tg)*D_);
            const int h = tid & 511;
            if (tid < 512) { ((float4*)Ks)[h] = kg[h]; ((float4*)Vs)[h] = vg[h]; }
            else           { ((float4*)Qs)[h] = qg[h]; }
        }
        __syncthreads();

        for (int tt = 0; tt < SUB_; tt++) {
            const int t = tg + tt;
            const int lt = sub*SUB_ + tt;       // 0..31 local row
            const float4 kv = *(const float4*)&Ks[tt*D_ + i0];
            const float4 vv = *(const float4*)&Vs[tt*D_ + j0];
            const float4 qv = *(const float4*)&Qs[tt*D_ + i0];
            const float kk[4] = {kv.x, kv.y, kv.z, kv.w};
            const float vb[4] = {vv.x, vv.y, vv.z, vv.w};
            const float qq[4] = {qv.x, qv.y, qv.z, qv.w};
            float p0 = 0.f, p1 = 0.f, p2 = 0.f, p3 = 0.f;
            float* orow = outS + (((size_t)b*T_ + t)*D_ + i0)*D_ + j0;
#pragma unroll
            for (int u = 0; u < 4; u++) {
                s[u][0] += kk[u]*vb[0];
                s[u][1] += kk[u]*vb[1];
                s[u][2] += kk[u]*vb[2];
                s[u][3] += kk[u]*vb[3];
                __stcs((float4*)(orow + (size_t)u*D_),
                       make_float4(s[u][0], s[u][1], s[u][2], s[u][3]));
                p0 += qq[u]*s[u][0];
                p1 += qq[u]*s[u][1];
                p2 += qq[u]*s[u][2];
                p3 += qq[u]*s[u][3];
            }
            float* pb = part + (tt & 1)*32*D_;
            *(float4*)&pb[ri*D_ + j0] = make_float4(p0, p1, p2, p3);
            if (tid < D_) {
                zrun += Ks[tt*D_ + tid];
                outZ[((size_t)b*T_ + t)*D_ + tid] = zrun;
            }
            __syncthreads();
            if (tid < D_) {
                float sum = 0.f;
#pragma unroll
                for (int rr = 0; rr < 32; rr++) sum += pb[rr*D_ + tid];
                numBuf[lt*D_ + tid] = sum;
            }
        }
        __syncthreads();
    }

    // ---- den per warp (Q from L2, Z just written by this block), a = num/den ----
    {
        const size_t row = (size_t)b*T_ + c*L_ + ri;
        const float4 q4 = __ldg((const float4*)(g_Q + row*D_) + jg);
        const float4 z4 = *((const float4*)(outZ + row*D_) + jg);
        float dv = q4.x*z4.x + q4.y*z4.y + q4.z*z4.z + q4.w*z4.w;
#pragma unroll
        for (int off = 16; off; off >>= 1) dv += __shfl_xor_sync(0xffffffffu, dv, off);
        const float rden = 1.0f / (dv + 1e-5f);
        float4 nv = *(float4*)&numBuf[ri*D_ + j0];
        nv.x *= rden; nv.y *= rden; nv.z *= rden; nv.w *= rden;
        *(float4*)&numBuf[ri*D_ + j0] = nv;
    }
    __syncthreads();

    // ---- FFN tail, k5 mapping: warps 0-7 compute (4 rows x 4 cols per thread) ----
    float* wbuf = part;            // [32][128]
    float* hbuf = part + 32*D_;    // [32][128]
    const int rowg = ri;           // valid for ri<8
    const int colg = jg;
    float acc[4][4];

    // GEMM1: h = relu(a @ W1 + b1)
#pragma unroll
    for (int u = 0; u < 4; u++)
#pragma unroll
        for (int v = 0; v < 4; v++) acc[u][v] = 0.f;
    for (int kc = 0; kc < D_; kc += 32) {
        __syncthreads();
        *(float4*)&wbuf[(tid >> 5)*D_ + (tid & 31)*4] =
            __ldg((const float4*)(W1 + (size_t)(kc + (tid >> 5))*D_) + (tid & 31));
        __syncthreads();
        if (ri < 8) {
#pragma unroll
            for (int k = 0; k < 32; k++) {
                const float4 wv = *(const float4*)&wbuf[k*D_ + colg*4];
#pragma unroll
                for (int u = 0; u < 4; u++) {
                    const float a = numBuf[(rowg*4+u)*D_ + kc + k];
                    acc[u][0] += a*wv.x; acc[u][1] += a*wv.y;
                    acc[u][2] += a*wv.z; acc[u][3] += a*wv.w;
                }
            }
        }
    }
    __syncthreads();
    if (ri < 8) {
        const float4 b1v = __ldg((const float4*)b1_ + colg);
#pragma unroll
        for (int u = 0; u < 4; u++) {
            float4 h;
            h.x = fmaxf(acc[u][0] + b1v.x, 0.f);
            h.y = fmaxf(acc[u][1] + b1v.y, 0.f);
            h.z = fmaxf(acc[u][2] + b1v.z, 0.f);
            h.w = fmaxf(acc[u][3] + b1v.w, 0.f);
            *(float4*)&hbuf[(rowg*4+u)*D_ + colg*4] = h;
        }
    }

    // GEMM2: o = relu(h @ W2 + b2) + R
#pragma unroll
    for (int u = 0; u < 4; u++)
#pragma unroll
        for (int v = 0; v < 4; v++) acc[u][v] = 0.f;
    for (int kc = 0; kc < D_; kc += 32) {
        __syncthreads();
        *(float4*)&wbuf[(tid >> 5)*D_ + (tid & 31)*4] =
            __ldg((const float4*)(W2 + (size_t)(kc + (tid >> 5))*D_) + (tid & 31));
        __syncthreads();
        if (ri < 8) {
#pragma unroll
            for (int k = 0; k < 32; k++) {
                const float4 wv = *(const float4*)&wbuf[k*D_ + colg*4];
#pragma unroll
                for (int u = 0; u < 4; u++) {
                    const float h = hbuf[(rowg*4+u)*D_ + kc + k];
                    acc[u][0] += h*wv.x; acc[u][1] += h*wv.y;
                    acc[u][2] += h*wv.z; acc[u][3] += h*wv.w;
                }
            }
        }
    }
    if (ri < 8) {
        const float4 b2v = __ldg((const float4*)b2_ + colg);
#pragma unroll
        for (int u = 0; u < 4; u++) {
            const size_t row = (size_t)b*T_ + c*L_ + rowg*4 + u;
            const float4 rv = *(const float4*)(g_R + row*D_ + colg*4);
            float4 o;
            o.x = fmaxf(acc[u][0] + b2v.x, 0.f) + rv.x;
            o.y = fmaxf(acc[u][1] + b2v.y, 0.f) + rv.y;
            o.z = fmaxf(acc[u][2] + b2v.z, 0.f) + rv.z;
            o.w = fmaxf(acc[u][3] + b2v.w, 0.f) + rv.w;
            *(float4*)(outO + row*D_ + colg*4) = o;
        }
    }
}

// ---------------- launch ----------------
extern "C" void kernel_launch(void* const* d_in, const int* in_sizes, int n_in,
                              void* d_out, int out_size) {
    const float* x     = (const float*)d_in[0];
    const float* S0    = (const float*)d_in[1];
    const float* Z0    = (const float*)d_in[2];
    const float* gamma = (const float*)d_in[3];
    const float* beta  = (const float*)d_in[4];
    const float* Wk    = (const float*)d_in[5];
    const float* Wq    = (const float*)d_in[6];
    const float* Wv    = (const float*)d_in[7];
    const float* W1    = (const float*)d_in[8];
    const float* b1    = (const float*)d_in[9];
    const float* W2    = (const float*)d_in[10];
    const float* b2    = (const float*)d_in[11];
    const float* Ws    = (const float*)d_in[12];
    const float* bs    = (const float*)d_in[13];

    float* outO = (float*)d_out;
    float* outS = outO + (size_t)B_*T_*D_;
    float* outZ = outS + (size_t)B_*T_*D_*D_;

    static bool attr_done = false;
    if (!attr_done) {
        cudaFuncSetAttribute(k4_main, cudaFuncAttributeMaxDynamicSharedMemorySize, K4_SMEM);
        cudaFuncSetAttribute(k1_tf32, cudaFuncAttributeMaxDynamicSharedMemorySize, K1_SMEM);
        attr_done = true;
    }

    k0_ln<<<(B_*T_)/32, 256>>>(x, gamma, beta);
    k1_tf32<<<dim3((B_*T_)/64, 4), 256, K1_SMEM>>>(Wk, Wq, Wv, Ws, bs);
    k2_chunksum<<<dim3(C_, B_), 256>>>();
    k4_main<<<dim3(C_, B_), 1024, K4_SMEM>>>(S0, Z0, W1, b1, W2, b2, outO, outS, outZ);
}

// round 15
// speedup vs baseline: 1.0984x; 1.0003x over previous
#include <cuda_runtime.h>
#include <math.h>
#include <stdint.h>

#define B_   8
#define T_   512
#define FIN_ 256
#define D_   128
#define C_   16          // chunks per batch
#define L_   32          // chunk length (T_/C_)
#define SUB_ 16          // sub-tile of timesteps in k4 smem

typedef unsigned long long u64;

// ---------------- scratch ----------------
__device__ __align__(16) float g_K[B_*T_*D_];
__device__ __align__(16) float g_Q[B_*T_*D_];
__device__ __align__(16) float g_V[B_*T_*D_];
__device__ __align__(16) float g_R[B_*T_*D_];
__device__ __align__(16) float g_Ssum[B_*C_*D_*D_];  // RAW per-chunk outer sums
__device__ __align__(16) float g_Zsum[B_*C_*D_];     // RAW per-chunk K sums

// ---------------- helpers ----------------
__device__ __forceinline__ uint32_t f2tf32(float x) {
    uint32_t r; asm("cvt.rna.tf32.f32 %0, %1;" : "=r"(r) : "f"(x)); return r;
}
__device__ __forceinline__ void mma_tf32(float* d, const uint32_t* a, const uint32_t* b) {
    asm volatile(
        "mma.sync.aligned.m16n8k8.row.col.f32.tf32.tf32.f32 "
        "{%0,%1,%2,%3}, {%4,%5,%6,%7}, {%8,%9}, {%0,%1,%2,%3};"
        : "+f"(d[0]), "+f"(d[1]), "+f"(d[2]), "+f"(d[3])
        : "r"(a[0]), "r"(a[1]), "r"(a[2]), "r"(a[3]), "r"(b[0]), "r"(b[1]));
}
__device__ __forceinline__ void fma2(u64& acc, u64 a, u64 b) {
    asm("fma.rn.f32x2 %0, %1, %2, %3;" : "=l"(acc) : "l"(a), "l"(b), "l"(acc));
}
__device__ __forceinline__ u64 bc2(float a) {
    u64 r; asm("mov.b64 %0, {%1, %1};" : "=l"(r) : "f"(a)); return r;
}
__device__ __forceinline__ float2 unp2(u64 v) {
    float2 r; asm("mov.b64 {%0, %1}, %2;" : "=f"(r.x), "=f"(r.y) : "l"(v)); return r;
}

// ---------------- k1: fused LayerNorm + tf32 projections (3xTF32 split) ----------------
// grid (64, 4) x 256. Block: 64 rows x 128 cols.
#define XP 36
#define WP 132
#define K1_SMEM ((2*64*XP + 2*32*WP + 128) * 4)
__global__ void __launch_bounds__(256)
k1_tf32(const float* __restrict__ x,
        const float* __restrict__ gamma, const float* __restrict__ beta,
        const float* __restrict__ Wk, const float* __restrict__ Wq,
        const float* __restrict__ Wv, const float* __restrict__ Ws,
        const float* __restrict__ bs) {
    extern __shared__ uint32_t su[];
    uint32_t* xh = su;
    uint32_t* xl = xh + 64*XP;
    uint32_t* wh = xl + 64*XP;
    uint32_t* wl = wh + 32*WP;
    float*    smu = (float*)(wl + 32*WP);   // [64]
    float*    srs = smu + 64;               // [64]

    const int tid  = threadIdx.x;
    const int lane = tid & 31;
    const int wid  = tid >> 5;
    const int wm   = wid >> 1;
    const int wn   = wid & 1;
    const int g    = lane >> 2;
    const int t    = lane & 3;
    const int row0 = blockIdx.x * 64;
    const int m    = blockIdx.y;

    const float* Wp = (m==0) ? Wk : (m==1) ? Wq : (m==2) ? Wv : Ws;
    float*       Op = (m==0) ? g_K : (m==1) ? g_Q : (m==2) ? g_V : g_R;

    // LN stats: warp wid owns rows wid*8 .. +8
#pragma unroll
    for (int rr = 0; rr < 8; rr++) {
        const int r = wid*8 + rr;
        const float* xr = x + ((size_t)row0 + r)*FIN_;
        float s = 0.f, ss = 0.f;
#pragma unroll
        for (int k = 0; k < 8; k++) {
            const float v = xr[lane + 32*k];
            s += v; ss += v*v;
        }
#pragma unroll
        for (int off = 16; off; off >>= 1) {
            s  += __shfl_xor_sync(0xffffffffu, s,  off);
            ss += __shfl_xor_sync(0xffffffffu, ss, off);
        }
        if (lane == 0) {
            const float mu = s * (1.0f/FIN_);
            smu[r] = mu;
            srs[r] = rsqrtf(ss*(1.0f/FIN_) - mu*mu + 1e-5f);
        }
    }

    float d[8][4];
#pragma unroll
    for (int nt = 0; nt < 8; nt++)
#pragma unroll
        for (int q = 0; q < 4; q++) d[nt][q] = 0.f;

    for (int kc = 0; kc < FIN_; kc += 32) {
        __syncthreads();
        // stage xn chunk (normalize on the fly): 64 rows x 32 k
#pragma unroll
        for (int p = 0; p < 2; p++) {
            const int idx = p*256 + tid;
            const int r = idx >> 3;
            const int col = kc + (idx & 7) * 4;
            const float4 xv = *(const float4*)(x + ((size_t)row0 + r)*FIN_ + col);
            const float4 gv = __ldg((const float4*)(gamma + col));
            const float4 bv = __ldg((const float4*)(beta + col));
            const float mu = smu[r], rs = srs[r];
            float4 v;
            v.x = (xv.x - mu)*rs*gv.x + bv.x;
            v.y = (xv.y - mu)*rs*gv.y + bv.y;
            v.z = (xv.z - mu)*rs*gv.z + bv.z;
            v.w = (xv.w - mu)*rs*gv.w + bv.w;
            uint4 h, l;
            h.x = f2tf32(v.x); l.x = f2tf32(v.x - __uint_as_float(h.x));
            h.y = f2tf32(v.y); l.y = f2tf32(v.y - __uint_as_float(h.y));
            h.z = f2tf32(v.z); l.z = f2tf32(v.z - __uint_as_float(h.z));
            h.w = f2tf32(v.w); l.w = f2tf32(v.w - __uint_as_float(h.w));
            const int c4 = (idx & 7) * 4;
            *(uint4*)&xh[r*XP + c4] = h;
            *(uint4*)&xl[r*XP + c4] = l;
        }
        // stage w chunk: 32 k x 128 n
#pragma unroll
        for (int p = 0; p < 4; p++) {
            const int idx = p*256 + tid;
            const int r = idx >> 5, c4 = (idx & 31) * 4;
            const float4 v = *(const float4*)(Wp + ((size_t)kc + r)*D_ + c4);
            uint4 h, l;
            h.x = f2tf32(v.x); l.x = f2tf32(v.x - __uint_as_float(h.x));
            h.y = f2tf32(v.y); l.y = f2tf32(v.y - __uint_as_float(h.y));
            h.z = f2tf32(v.z); l.z = f2tf32(v.z - __uint_as_float(h.z));
            h.w = f2tf32(v.w); l.w = f2tf32(v.w - __uint_as_float(h.w));
            *(uint4*)&wh[r*WP + c4] = h;
            *(uint4*)&wl[r*WP + c4] = l;
        }
        __syncthreads();

#pragma unroll
        for (int ks = 0; ks < 4; ks++) {
            const int ko = ks * 8;
            const int m0 = wm * 16;
            uint32_t ah[4], al[4];
            ah[0] = xh[(m0+g)*XP   + ko + t];
            ah[1] = xh[(m0+g+8)*XP + ko + t];
            ah[2] = xh[(m0+g)*XP   + ko + t + 4];
            ah[3] = xh[(m0+g+8)*XP + ko + t + 4];
            al[0] = xl[(m0+g)*XP   + ko + t];
            al[1] = xl[(m0+g+8)*XP + ko + t];
            al[2] = xl[(m0+g)*XP   + ko + t + 4];
            al[3] = xl[(m0+g+8)*XP + ko + t + 4];
#pragma unroll
            for (int nt = 0; nt < 8; nt++) {
                const int n0 = wn*64 + nt*8;
                uint32_t bh[2], bl[2];
                bh[0] = wh[(ko+t)*WP   + n0 + g];
                bh[1] = wh[(ko+t+4)*WP + n0 + g];
                bl[0] = wl[(ko+t)*WP   + n0 + g];
                bl[1] = wl[(ko+t+4)*WP + n0 + g];
                mma_tf32(d[nt], ah, bh);
                mma_tf32(d[nt], ah, bl);
                mma_tf32(d[nt], al, bh);
            }
        }
    }

#pragma unroll
    for (int nt = 0; nt < 8; nt++) {
        const int n0 = wn*64 + nt*8;
        const int cA = n0 + t*2;
        float v0 = d[nt][0], v1 = d[nt][1], v2 = d[nt][2], v3 = d[nt][3];
        if (m <= 1) {
            v0 = (v0 > 0.f) ? (v0 + 1.f) : expf(v0);
            v1 = (v1 > 0.f) ? (v1 + 1.f) : expf(v1);
            v2 = (v2 > 0.f) ? (v2 + 1.f) : expf(v2);
            v3 = (v3 > 0.f) ? (v3 + 1.f) : expf(v3);
        } else if (m == 3) {
            const float b0 = bs[cA], b1 = bs[cA+1];
            v0 += b0; v1 += b1; v2 += b0; v3 += b1;
        }
        const size_t r0 = (size_t)row0 + wm*16 + g;
        *(float2*)(Op + r0*D_ + cA)       = make_float2(v0, v1);
        *(float2*)(Op + (r0+8)*D_ + cA)   = make_float2(v2, v3);
    }
}

// ---------------- k2: per-chunk outer-product sums + K sums (f32x2 micro) ----------------
__global__ void k2_chunksum() {
    const int c = blockIdx.x, b = blockIdx.y;
    const int tid = threadIdx.x;   // 256
    __shared__ __align__(16) float Ks[L_][D_];
    __shared__ __align__(16) float Vs[L_][D_];
    {
        const float4* kg = (const float4*)(g_K + ((size_t)b*T_ + c*L_)*D_);
        const float4* vg = (const float4*)(g_V + ((size_t)b*T_ + c*L_)*D_);
        for (int q = tid; q < L_*D_/4; q += 256) { ((float4*)Ks)[q] = kg[q]; ((float4*)Vs)[q] = vg[q]; }
    }
    __syncthreads();

    if (tid < D_) {
        float zs = 0.f;
#pragma unroll
        for (int t = 0; t < L_; t++) zs += Ks[t][tid];
        g_Zsum[((size_t)(b*C_ + c))*D_ + tid] = zs;
    }

    const int tr = tid >> 4, tc = tid & 15;
    const int i0 = tr*8, j0 = tc*8;
    u64 acc2[8][4];
#pragma unroll
    for (int u = 0; u < 8; u++)
#pragma unroll
        for (int p = 0; p < 4; p++) acc2[u][p] = 0ull;

    for (int t = 0; t < L_; t++) {
        float k8[8];
        *(float4*)(k8)   = *(const float4*)&Ks[t][i0];
        *(float4*)(k8+4) = *(const float4*)&Ks[t][i0+4];
        const ulonglong2 vA = *(const ulonglong2*)&Vs[t][j0];
        const ulonglong2 vB = *(const ulonglong2*)&Vs[t][j0+4];
#pragma unroll
        for (int u = 0; u < 8; u++) {
            const u64 a = bc2(k8[u]);
            fma2(acc2[u][0], a, vA.x);
            fma2(acc2[u][1], a, vA.y);
            fma2(acc2[u][2], a, vB.x);
            fma2(acc2[u][3], a, vB.y);
        }
    }
    float* op = g_Ssum + (((size_t)(b*C_ + c))*D_ + i0)*D_ + j0;
#pragma unroll
    for (int u = 0; u < 8; u++) {
        const float2 a0 = unp2(acc2[u][0]);
        const float2 a1 = unp2(acc2[u][1]);
        const float2 a2 = unp2(acc2[u][2]);
        const float2 a3 = unp2(acc2[u][3]);
        *(float4*)(op + (size_t)u*D_)     = make_float4(a0.x, a0.y, a1.x, a1.y);
        *(float4*)(op + (size_t)u*D_ + 4) = make_float4(a2.x, a2.y, a3.x, a3.y);
    }
}

// ---------------- k4: fused scan + num (smem) + den + FFN tail (f32x2, 4x4 map) ----------------
#define K4_SMEM ((3*SUB_*D_ + 2*32*D_ + 32*D_) * (int)sizeof(float))   // 73728
__global__ void __launch_bounds__(1024, 1)
k4_main(const float* __restrict__ S0, const float* __restrict__ Z0,
        const float* __restrict__ W1, const float* __restrict__ b1_,
        const float* __restrict__ W2, const float* __restrict__ b2_,
        float* __restrict__ outO, float* __restrict__ outS, float* __restrict__ outZ) {
    const int c = blockIdx.x, b = blockIdx.y;
    const int tid = threadIdx.x;         // 1024
    const int ri = tid >> 5;             // 0..31
    const int jg = tid & 31;             // 0..31
    const int i0 = ri << 2, j0 = jg << 2;

    extern __shared__ float dsm[];
    float* Ks     = dsm;                        // [SUB_][D_]
    float* Vs     = Ks + SUB_*D_;
    float* Qs     = Vs + SUB_*D_;
    float* part   = Qs + SUB_*D_;               // [2][32][D_] — scan partials; tail: wbuf+hbuf
    float* numBuf = part + 2*32*D_;             // [32][D_]

    // init: S0 + sum of raw chunk sums c' < c
    float s[4][4];
    {
        const float* s0g = S0 + ((size_t)b*D_ + i0)*D_ + j0;
#pragma unroll
        for (int u = 0; u < 4; u++) {
            const float4 z = *(const float4*)(s0g + (size_t)u*D_);
            s[u][0] = z.x; s[u][1] = z.y; s[u][2] = z.z; s[u][3] = z.w;
        }
        for (int c2 = 0; c2 < c; c2++) {
            const float* sp = g_Ssum + ((size_t)(b*C_ + c2)*D_ + i0)*D_ + j0;
#pragma unroll
            for (int u = 0; u < 4; u++) {
                const float4 a = __ldg((const float4*)(sp + (size_t)u*D_));
                s[u][0] += a.x; s[u][1] += a.y; s[u][2] += a.z; s[u][3] += a.w;
            }
        }
    }

    float zrun = 0.f;
    if (tid < D_) {
        zrun = Z0[b*D_ + tid];
        for (int c2 = 0; c2 < c; c2++)
            zrun += g_Zsum[(size_t)(b*C_ + c2)*D_ + tid];
    }

    const int t0 = c * L_;
    for (int sub = 0; sub < L_/SUB_; sub++) {
        const int tg = t0 + sub*SUB_;
        {
            const float4* kg = (const float4*)(g_K + ((size_t)b*T_ + tg)*D_);
            const float4* vg = (const float4*)(g_V + ((size_t)b*T_ + tg)*D_);
            const float4* qg = (const float4*)(g_Q + ((size_t)b*T_ + tg)*D_);
            const int h = tid & 511;
            if (tid < 512) { ((float4*)Ks)[h] = kg[h]; ((float4*)Vs)[h] = vg[h]; }
            else           { ((float4*)Qs)[h] = qg[h]; }
        }
        __syncthreads();

        for (int tt = 0; tt < SUB_; tt++) {
            const int t = tg + tt;
            const int lt = sub*SUB_ + tt;       // 0..31 local row
            const float4 kv = *(const float4*)&Ks[tt*D_ + i0];
            const float4 vv = *(const float4*)&Vs[tt*D_ + j0];
            const float4 qv = *(const float4*)&Qs[tt*D_ + i0];
            const float kk[4] = {kv.x, kv.y, kv.z, kv.w};
            const float vb[4] = {vv.x, vv.y, vv.z, vv.w};
            const float qq[4] = {qv.x, qv.y, qv.z, qv.w};
            float p0 = 0.f, p1 = 0.f, p2 = 0.f, p3 = 0.f;
            float* orow = outS + (((size_t)b*T_ + t)*D_ + i0)*D_ + j0;
#pragma unroll
            for (int u = 0; u < 4; u++) {
                s[u][0] += kk[u]*vb[0];
                s[u][1] += kk[u]*vb[1];
                s[u][2] += kk[u]*vb[2];
                s[u][3] += kk[u]*vb[3];
                __stcs((float4*)(orow + (size_t)u*D_),
                       make_float4(s[u][0], s[u][1], s[u][2], s[u][3]));
                p0 += qq[u]*s[u][0];
                p1 += qq[u]*s[u][1];
                p2 += qq[u]*s[u][2];
                p3 += qq[u]*s[u][3];
            }
            float* pb = part + (tt & 1)*32*D_;
            *(float4*)&pb[ri*D_ + j0] = make_float4(p0, p1, p2, p3);
            if (tid < D_) {
                zrun += Ks[tt*D_ + tid];
                outZ[((size_t)b*T_ + t)*D_ + tid] = zrun;
            }
            __syncthreads();
            if (tid < D_) {
                float sum = 0.f;
#pragma unroll
                for (int rr = 0; rr < 32; rr++) sum += pb[rr*D_ + tid];
                numBuf[lt*D_ + tid] = sum;
            }
        }
        __syncthreads();
    }

    // ---- den per warp, a = num/den ----
    {
        const size_t row = (size_t)b*T_ + c*L_ + ri;
        const float4 q4 = __ldg((const float4*)(g_Q + row*D_) + jg);
        const float4 z4 = *((const float4*)(outZ + row*D_) + jg);
        float dv = q4.x*z4.x + q4.y*z4.y + q4.z*z4.z + q4.w*z4.w;
#pragma unroll
        for (int off = 16; off; off >>= 1) dv += __shfl_xor_sync(0xffffffffu, dv, off);
        const float rden = 1.0f / (dv + 1e-5f);
        float4 nv = *(float4*)&numBuf[ri*D_ + j0];
        nv.x *= rden; nv.y *= rden; nv.z *= rden; nv.w *= rden;
        *(float4*)&numBuf[ri*D_ + j0] = nv;
    }
    __syncthreads();

    // ---- FFN tail: warps 0-7 compute (4 rows x 4 cols per thread), f32x2 FMA ----
    float* wbuf = part;            // [32][128]
    float* hbuf = part + 32*D_;    // [32][128]
    const int rowg = ri;           // valid for ri<8
    const int colg = jg;
    u64 acc2[4][2];

    // GEMM1: h = relu(a @ W1 + b1)
#pragma unroll
    for (int u = 0; u < 4; u++) { acc2[u][0] = 0ull; acc2[u][1] = 0ull; }
    for (int kc = 0; kc < D_; kc += 32) {
        __syncthreads();
        *(float4*)&wbuf[(tid >> 5)*D_ + (tid & 31)*4] =
            __ldg((const float4*)(W1 + (size_t)(kc + (tid >> 5))*D_) + (tid & 31));
        __syncthreads();
        if (ri < 8) {
#pragma unroll
            for (int k = 0; k < 32; k++) {
                const ulonglong2 wv = *(const ulonglong2*)&wbuf[k*D_ + colg*4];
#pragma unroll
                for (int u = 0; u < 4; u++) {
                    const u64 a = bc2(numBuf[(rowg*4+u)*D_ + kc + k]);
                    fma2(acc2[u][0], a, wv.x);
                    fma2(acc2[u][1], a, wv.y);
                }
            }
        }
    }
    __syncthreads();
    if (ri < 8) {
        const float4 b1v = __ldg((const float4*)b1_ + colg);
#pragma unroll
        for (int u = 0; u < 4; u++) {
            const float2 a0 = unp2(acc2[u][0]);
            const float2 a1 = unp2(acc2[u][1]);
            float4 h;
            h.x = fmaxf(a0.x + b1v.x, 0.f);
            h.y = fmaxf(a0.y + b1v.y, 0.f);
            h.z = fmaxf(a1.x + b1v.z, 0.f);
            h.w = fmaxf(a1.y + b1v.w, 0.f);
            *(float4*)&hbuf[(rowg*4+u)*D_ + colg*4] = h;
        }
    }

    // GEMM2: o = relu(h @ W2 + b2) + R
#pragma unroll
    for (int u = 0; u < 4; u++) { acc2[u][0] = 0ull; acc2[u][1] = 0ull; }
    for (int kc = 0; kc < D_; kc += 32) {
        __syncthreads();
        *(float4*)&wbuf[(tid >> 5)*D_ + (tid & 31)*4] =
            __ldg((const float4*)(W2 + (size_t)(kc + (tid >> 5))*D_) + (tid & 31));
        __syncthreads();
        if (ri < 8) {
#pragma unroll
            for (int k = 0; k < 32; k++) {
                const ulonglong2 wv = *(const ulonglong2*)&wbuf[k*D_ + colg*4];
#pragma unroll
                for (int u = 0; u < 4; u++) {
                    const u64 h = bc2(hbuf[(rowg*4+u)*D_ + kc + k]);
                    fma2(acc2[u][0], h, wv.x);
                    fma2(acc2[u][1], h, wv.y);
                }
            }
        }
    }
    if (ri < 8) {
        const float4 b2v = __ldg((const float4*)b2_ + colg);
#pragma unroll
        for (int u = 0; u < 4; u++) {
            const size_t row = (size_t)b*T_ + c*L_ + rowg*4 + u;
            const float4 rv = *(const float4*)(g_R + row*D_ + colg*4);
            const float2 a0 = unp2(acc2[u][0]);
            const float2 a1 = unp2(acc2[u][1]);
            float4 o;
            o.x = fmaxf(a0.x + b2v.x, 0.f) + rv.x;
            o.y = fmaxf(a0.y + b2v.y, 0.f) + rv.y;
            o.z = fmaxf(a1.x + b2v.z, 0.f) + rv.z;
            o.w = fmaxf(a1.y + b2v.w, 0.f) + rv.w;
            *(float4*)(outO + row*D_ + colg*4) = o;
        }
    }
}

// ---------------- launch ----------------
extern "C" void kernel_launch(void* const* d_in, const int* in_sizes, int n_in,
                              void* d_out, int out_size) {
    const float* x     = (const float*)d_in[0];
    const float* S0    = (const float*)d_in[1];
    const float* Z0    = (const float*)d_in[2];
    const float* gamma = (const float*)d_in[3];
    const float* beta  = (const float*)d_in[4];
    const float* Wk    = (const float*)d_in[5];
    const float* Wq    = (const float*)d_in[6];
    const float* Wv    = (const float*)d_in[7];
    const float* W1    = (const float*)d_in[8];
    const float* b1    = (const float*)d_in[9];
    const float* W2    = (const float*)d_in[10];
    const float* b2    = (const float*)d_in[11];
    const float* Ws    = (const float*)d_in[12];
    const float* bs    = (const float*)d_in[13];

    float* outO = (float*)d_out;
    float* outS = outO + (size_t)B_*T_*D_;
    float* outZ = outS + (size_t)B_*T_*D_*D_;

    static bool attr_done = false;
    if (!attr_done) {
        cudaFuncSetAttribute(k4_main, cudaFuncAttributeMaxDynamicSharedMemorySize, K4_SMEM);
        cudaFuncSetAttribute(k1_tf32, cudaFuncAttributeMaxDynamicSharedMemorySize, K1_SMEM);
        attr_done = true;
    }

    k1_tf32<<<dim3((B_*T_)/64, 4), 256, K1_SMEM>>>(x, gamma, beta, Wk, Wq, Wv, Ws, bs);
    k2_chunksum<<<dim3(C_, B_), 256>>>();
    k4_main<<<dim3(C_, B_), 1024, K4_SMEM>>>(S0, Z0, W1, b1, W2, b2, outO, outS, outZ);
}